// round 15
// baseline (speedup 1.0000x reference)
#include <cuda_runtime.h>
#include <cstdint>
#include <cstddef>

#define NN 100000
#define NE 1600000
#define SCAN_B ((NN + 255) / 256)   // 391

typedef unsigned long long ull;

// ---------------- scratch (device globals; zero-initialized at load) ----------------
static __device__ float  g_y[(size_t)NN * 384];     // t buffers [N,K*in] / decoder hidden
static __device__ float  g_h1[(size_t)NN * 128];    // h1
static __device__ float  g_h2[(size_t)NN * 64];     // h2; later z
static __device__ float4 g_ecsr[NE];                // CSR-ordered {c0,c1,c2, src-as-bits}
static __device__ int    g_off[NN + 1];
static __device__ int    g_cur[NN];
static __device__ int    g_deg[NN];
static __device__ float  g_dinv[NN];
static __device__ float  g_w3T[192 * 128];          // [k*64+i][mu 0..63 | logvar 64..127]
static __device__ int    g_bsum[512];
static __device__ int    g_boff[512];
static __device__ int    g_is64;

// ---------------- fused prep: dtype detect + w3 interleave + zero degrees ----------------
__global__ void k_prep(const int* __restrict__ ei32, const float* __restrict__ mw,
                       const float* __restrict__ lw) {
    int idx = blockIdx.x * 256 + threadIdx.x;
    if (blockIdx.x == 0) {
        int nz = (ei32[2 * threadIdx.x + 1] != 0) ? 1 : 0;
        int any = __syncthreads_or(nz);
        if (threadIdx.x == 0) g_is64 = any ? 0 : 1;
    }
    if (idx < 3 * 64 * 64) {
        int o = idx & 63;
        int r = idx >> 6;
        g_w3T[r * 128 + o]      = mw[idx];
        g_w3T[r * 128 + 64 + o] = lw[idx];
    }
    if (idx < NN) g_deg[idx] = 0;
}

__device__ __forceinline__ int load_idx(const void* eiv, size_t pos) {
    if (g_is64) return (int)((const long long*)eiv)[pos];
    return ((const int*)eiv)[pos];
}

__global__ void k_deg(const void* __restrict__ eiv) {
    int e = blockIdx.x * blockDim.x + threadIdx.x;
    if (e >= NE) return;
    int d = load_idx(eiv, (size_t)NE + e);
    d = min(max(d, 0), NN - 1);
    atomicAdd(&g_deg[d], 1);
}

// ---------------- two-level scan ----------------
__global__ void k_scan1() {
    __shared__ int ws[8];
    int i = blockIdx.x * 256 + threadIdx.x;
    int lane = threadIdx.x & 31, wid = threadIdx.x >> 5;
    int v = (i < NN) ? g_deg[i] : 0;
    int s = v;
#pragma unroll
    for (int o = 1; o < 32; o <<= 1) {
        int t = __shfl_up_sync(0xFFFFFFFFu, s, o);
        if (lane >= o) s += t;
    }
    if (lane == 31) ws[wid] = s;
    __syncthreads();
    if (threadIdx.x == 0) {
        int tot = 0;
#pragma unroll
        for (int w = 0; w < 8; w++) tot += ws[w];
        g_bsum[blockIdx.x] = tot;
    }
}

__global__ void k_scan2() {
    __shared__ int ws[16];
    int tid = threadIdx.x, lane = tid & 31, wid = tid >> 5;
    int v = (tid < SCAN_B) ? g_bsum[tid] : 0;
    int s = v;
#pragma unroll
    for (int o = 1; o < 32; o <<= 1) {
        int t = __shfl_up_sync(0xFFFFFFFFu, s, o);
        if (lane >= o) s += t;
    }
    if (lane == 31) ws[wid] = s;
    __syncthreads();
    if (wid == 0 && lane < 16) {
        int a = ws[lane];
        int si = a;
#pragma unroll
        for (int o = 1; o < 16; o <<= 1) {
            int t = __shfl_up_sync(0xFFFFu, si, o);
            if (lane >= o) si += t;
        }
        ws[lane] = si - a;
    }
    __syncthreads();
    int incl = ws[wid] + s;
    if (tid < SCAN_B) g_boff[tid] = incl - v;
    if (tid == SCAN_B - 1) g_off[NN] = incl;
}

__global__ void k_scan3() {
    __shared__ int ws[8];
    int i = blockIdx.x * 256 + threadIdx.x;
    int lane = threadIdx.x & 31, wid = threadIdx.x >> 5;
    int v = (i < NN) ? g_deg[i] : 0;
    int s = v;
#pragma unroll
    for (int o = 1; o < 32; o <<= 1) {
        int t = __shfl_up_sync(0xFFFFFFFFu, s, o);
        if (lane >= o) s += t;
    }
    if (lane == 31) ws[wid] = s;
    __syncthreads();
    if (wid == 0 && lane < 8) {
        int a = ws[lane];
        int si = a;
#pragma unroll
        for (int o = 1; o < 8; o <<= 1) {
            int t = __shfl_up_sync(0xFFu, si, o);
            if (lane >= o) si += t;
        }
        ws[lane] = si - a;
    }
    __syncthreads();
    if (i < NN) {
        int excl = g_boff[blockIdx.x] + ws[wid] + s - v;
        g_off[i] = excl;
        g_cur[i] = excl;
        g_dinv[i] = 1.0f / fmaxf((float)v, 1.0f);
    }
}

__global__ void k_place(const void* __restrict__ eiv, const float* __restrict__ pseudo) {
    int e = blockIdx.x * blockDim.x + threadIdx.x;
    if (e >= NE) return;
    int s = load_idx(eiv, e);
    int d = load_idx(eiv, (size_t)NE + e);
    s = min(max(s, 0), NN - 1);
    d = min(max(d, 0), NN - 1);
    float p  = pseudo[e];
    float v  = p * 3.0f;
    float fl = floorf(v);
    float f  = v - fl;
    int bot  = ((int)fl) % 3;
    float b0 = 0.5f * f * f - f + 0.5f;
    float b1 = -f * f + f + 0.5f;
    float b2 = 0.5f * f * f;
    float c0, c1, c2;
    if (bot == 0)      { c0 = b0; c1 = b1; c2 = b2; }
    else if (bot == 1) { c0 = b2; c1 = b0; c2 = b1; }
    else               { c0 = b1; c1 = b2; c2 = b0; }
    int pos = atomicAdd(&g_cur[d], 1);
    g_ecsr[pos] = make_float4(c0, c1, c2, __int_as_float(s));
}

// ---------------- CSR in-domain aggregation ----------------
#define AGG_FMA(a0, a1, a2, m, v)                                            \
    a0.x += m.x * v.x; a0.y += m.x * v.y; a0.z += m.x * v.z; a0.w += m.x * v.w; \
    a1.x += m.y * v.x; a1.y += m.y * v.y; a1.z += m.y * v.z; a1.w += m.y * v.w; \
    a2.x += m.z * v.x; a2.y += m.z * v.y; a2.z += m.z * v.z; a2.w += m.z * v.w;

// in=64: FULL warp per dst; half-warps process even/odd edges (stride 2, unroll 4),
// combined at the end via shfl_xor(16). 8 gathers in flight per warp, no half-vs-half
// trip-count divergence beyond 1 edge.
__global__ void k_agg64(const float* __restrict__ h, float* __restrict__ t) {
    int lane = threadIdx.x & 31;
    int half = lane >> 4;          // 0: even edges, 1: odd edges
    int sub  = lane & 15;
    int dst  = (blockIdx.x * blockDim.x + threadIdx.x) >> 5;
    if (dst >= NN) return;
    int beg = g_off[dst], end = g_off[dst + 1];
    float4 a0 = make_float4(0.f, 0.f, 0.f, 0.f), a1 = a0, a2 = a0;
    int p = beg + half;
    for (; p + 6 < end; p += 8) {   // 4 edges per half per iter: p, p+2, p+4, p+6
        float4 m0 = g_ecsr[p], m1 = g_ecsr[p + 2], m2 = g_ecsr[p + 4], m3 = g_ecsr[p + 6];
        float4 v0 = *reinterpret_cast<const float4*>(h + ((size_t)__float_as_int(m0.w)) * 64 + sub * 4);
        float4 v1 = *reinterpret_cast<const float4*>(h + ((size_t)__float_as_int(m1.w)) * 64 + sub * 4);
        float4 v2 = *reinterpret_cast<const float4*>(h + ((size_t)__float_as_int(m2.w)) * 64 + sub * 4);
        float4 v3 = *reinterpret_cast<const float4*>(h + ((size_t)__float_as_int(m3.w)) * 64 + sub * 4);
        AGG_FMA(a0, a1, a2, m0, v0)
        AGG_FMA(a0, a1, a2, m1, v1)
        AGG_FMA(a0, a1, a2, m2, v2)
        AGG_FMA(a0, a1, a2, m3, v3)
    }
    for (; p < end; p += 2) {
        float4 m = g_ecsr[p];
        float4 v = *reinterpret_cast<const float4*>(h + ((size_t)__float_as_int(m.w)) * 64 + sub * 4);
        AGG_FMA(a0, a1, a2, m, v)
    }
    // combine even/odd halves
    a0.x += __shfl_xor_sync(0xFFFFFFFFu, a0.x, 16);
    a0.y += __shfl_xor_sync(0xFFFFFFFFu, a0.y, 16);
    a0.z += __shfl_xor_sync(0xFFFFFFFFu, a0.z, 16);
    a0.w += __shfl_xor_sync(0xFFFFFFFFu, a0.w, 16);
    a1.x += __shfl_xor_sync(0xFFFFFFFFu, a1.x, 16);
    a1.y += __shfl_xor_sync(0xFFFFFFFFu, a1.y, 16);
    a1.z += __shfl_xor_sync(0xFFFFFFFFu, a1.z, 16);
    a1.w += __shfl_xor_sync(0xFFFFFFFFu, a1.w, 16);
    a2.x += __shfl_xor_sync(0xFFFFFFFFu, a2.x, 16);
    a2.y += __shfl_xor_sync(0xFFFFFFFFu, a2.y, 16);
    a2.z += __shfl_xor_sync(0xFFFFFFFFu, a2.z, 16);
    a2.w += __shfl_xor_sync(0xFFFFFFFFu, a2.w, 16);
    float4* tr = reinterpret_cast<float4*>(t + (size_t)dst * 192);
    if (half == 0) {
        tr[sub] = a0;
        tr[16 + sub] = a1;
    } else {
        tr[32 + sub] = a2;
    }
}

__global__ void k_agg128(const float* __restrict__ h, float* __restrict__ t) {
    int lane = threadIdx.x & 31;
    int dst  = (blockIdx.x * blockDim.x + threadIdx.x) >> 5;
    if (dst >= NN) return;
    int p = g_off[dst], end = g_off[dst + 1];
    float4 a0 = make_float4(0.f, 0.f, 0.f, 0.f), a1 = a0, a2 = a0;
    for (; p + 3 < end; p += 4) {
        float4 m0 = g_ecsr[p], m1 = g_ecsr[p + 1], m2 = g_ecsr[p + 2], m3 = g_ecsr[p + 3];
        float4 v0 = *reinterpret_cast<const float4*>(h + ((size_t)__float_as_int(m0.w)) * 128 + lane * 4);
        float4 v1 = *reinterpret_cast<const float4*>(h + ((size_t)__float_as_int(m1.w)) * 128 + lane * 4);
        float4 v2 = *reinterpret_cast<const float4*>(h + ((size_t)__float_as_int(m2.w)) * 128 + lane * 4);
        float4 v3 = *reinterpret_cast<const float4*>(h + ((size_t)__float_as_int(m3.w)) * 128 + lane * 4);
        AGG_FMA(a0, a1, a2, m0, v0)
        AGG_FMA(a0, a1, a2, m1, v1)
        AGG_FMA(a0, a1, a2, m2, v2)
        AGG_FMA(a0, a1, a2, m3, v3)
    }
    for (; p < end; p++) {
        float4 m = g_ecsr[p];
        float4 v = *reinterpret_cast<const float4*>(h + ((size_t)__float_as_int(m.w)) * 128 + lane * 4);
        AGG_FMA(a0, a1, a2, m, v)
    }
    float4* tr = reinterpret_cast<float4*>(t + (size_t)dst * 384);
    tr[lane] = a0; tr[32 + lane] = a1; tr[64 + lane] = a2;
}

// ---------------- GEMM: packed f32x2 math + register double-buffering (750.3µs-proven) ----------------
// C[M,TN] = A[M,K] @ B[K,TN], TM=128, TK=32, 256 threads, 8 rows x TN/16 cols/thread.
// epi: 0 none, 1 bias+relu, 2 bias, 3 row-scale dinv, 4 fused mu/logvar/z (TN=128 only)
template <int TN>
__global__ __launch_bounds__(256, 2) void k_gemm2(
    const float* __restrict__ A, const float* __restrict__ B,
    const float* __restrict__ bias, float* __restrict__ C, int M, int K, int epi,
    const float* __restrict__ eps, float* __restrict__ outmlv, float* __restrict__ zout) {
    constexpr int TK = 32;
    constexpr int NPAIR = TN / 32;
    constexpr int NB = TN / 32;
    __shared__ float As[TK * 132];
    __shared__ float Bs[TK * TN];

    int tid = threadIdx.x;
    int tx  = tid & 15;
    int ty  = tid >> 4;
    int m0  = blockIdx.x * 128;

    float  ar[16];
    float4 br[NB];

#pragma unroll
    for (int i = 0; i < 16; i++) {
        int idx = tid + i * 256;
        int gm = m0 + (idx >> 5);
        ar[i] = (gm < M) ? A[(size_t)gm * K + (idx & 31)] : 0.0f;
    }
#pragma unroll
    for (int i = 0; i < NB; i++) {
        int idx = tid + i * 256;
        br[i] = *reinterpret_cast<const float4*>(&B[(size_t)(idx / (TN / 4)) * TN + (idx % (TN / 4)) * 4]);
    }

    ull acc[8][NPAIR];
#pragma unroll
    for (int r = 0; r < 8; r++)
#pragma unroll
        for (int c = 0; c < NPAIR; c++) acc[r][c] = 0ull;

    for (int kc = 0; kc < K; kc += TK) {
#pragma unroll
        for (int i = 0; i < 16; i++) {
            int idx = tid + i * 256;
            As[(idx & 31) * 132 + (idx >> 5)] = ar[i];
        }
#pragma unroll
        for (int i = 0; i < NB; i++) {
            int idx = tid + i * 256;
            *reinterpret_cast<float4*>(&Bs[(idx / (TN / 4)) * TN + (idx % (TN / 4)) * 4]) = br[i];
        }
        __syncthreads();
        if (kc + TK < K) {
            int kn = kc + TK;
#pragma unroll
            for (int i = 0; i < 16; i++) {
                int idx = tid + i * 256;
                int gm = m0 + (idx >> 5);
                ar[i] = (gm < M) ? A[(size_t)gm * K + kn + (idx & 31)] : 0.0f;
            }
#pragma unroll
            for (int i = 0; i < NB; i++) {
                int idx = tid + i * 256;
                br[i] = *reinterpret_cast<const float4*>(&B[(size_t)(kn + idx / (TN / 4)) * TN + (idx % (TN / 4)) * 4]);
            }
        }
#pragma unroll 8
        for (int k = 0; k < TK; k++) {
            float4 a0 = *reinterpret_cast<const float4*>(&As[k * 132 + ty * 8]);
            float4 a1 = *reinterpret_cast<const float4*>(&As[k * 132 + ty * 8 + 4]);
            float am[8] = {a0.x, a0.y, a0.z, a0.w, a1.x, a1.y, a1.z, a1.w};
            ull ap[8];
#pragma unroll
            for (int r = 0; r < 8; r++)
                asm("mov.b64 %0, {%1, %1};" : "=l"(ap[r]) : "f"(am[r]));
            ulonglong2 b0 = *reinterpret_cast<const ulonglong2*>(&Bs[k * TN + tx * 4]);
#pragma unroll
            for (int r = 0; r < 8; r++) {
                asm("fma.rn.f32x2 %0, %1, %2, %0;" : "+l"(acc[r][0]) : "l"(ap[r]), "l"(b0.x));
                asm("fma.rn.f32x2 %0, %1, %2, %0;" : "+l"(acc[r][1]) : "l"(ap[r]), "l"(b0.y));
            }
            if (TN == 128) {
                ulonglong2 b1 = *reinterpret_cast<const ulonglong2*>(&Bs[k * TN + 64 + tx * 4]);
#pragma unroll
                for (int r = 0; r < 8; r++) {
                    asm("fma.rn.f32x2 %0, %1, %2, %0;" : "+l"(acc[r][NPAIR - 2]) : "l"(ap[r]), "l"(b1.x));
                    asm("fma.rn.f32x2 %0, %1, %2, %0;" : "+l"(acc[r][NPAIR - 1]) : "l"(ap[r]), "l"(b1.y));
                }
            }
        }
        __syncthreads();
    }

    // ---------------- epilogue ----------------
    if (epi == 4) {  // fused: mu | logvar -> outmlv, z -> zout  (TN==128)
        const size_t n64 = (size_t)NN * 64;
#pragma unroll
        for (int r = 0; r < 8; r++) {
            int m = m0 + ty * 8 + r;
            if (m >= M) continue;
            float rs = g_dinv[m];
            float mu0, mu1, mu2, mu3, lv0, lv1, lv2, lv3;
            asm("mov.b64 {%0, %1}, %2;" : "=f"(mu0), "=f"(mu1) : "l"(acc[r][0]));
            asm("mov.b64 {%0, %1}, %2;" : "=f"(mu2), "=f"(mu3) : "l"(acc[r][1]));
            asm("mov.b64 {%0, %1}, %2;" : "=f"(lv0), "=f"(lv1) : "l"(acc[r][NPAIR - 2]));
            asm("mov.b64 {%0, %1}, %2;" : "=f"(lv2), "=f"(lv3) : "l"(acc[r][NPAIR - 1]));
            mu0 *= rs; mu1 *= rs; mu2 *= rs; mu3 *= rs;
            lv0 *= rs; lv1 *= rs; lv2 *= rs; lv3 *= rs;
            size_t base = (size_t)m * 64 + tx * 4;
            float4 ev = *reinterpret_cast<const float4*>(&eps[base]);
            float4 zv;
            zv.x = mu0 + ev.x * expf(0.5f * lv0);
            zv.y = mu1 + ev.y * expf(0.5f * lv1);
            zv.z = mu2 + ev.z * expf(0.5f * lv2);
            zv.w = mu3 + ev.w * expf(0.5f * lv3);
            *reinterpret_cast<float4*>(&outmlv[n64 + base])     = make_float4(mu0, mu1, mu2, mu3);
            *reinterpret_cast<float4*>(&outmlv[2 * n64 + base]) = make_float4(lv0, lv1, lv2, lv3);
            *reinterpret_cast<float4*>(&zout[base]) = zv;
        }
        return;
    }

    float4 bv0 = make_float4(0.f, 0.f, 0.f, 0.f), bv1 = bv0;
    if (epi == 1 || epi == 2) {
        bv0 = *reinterpret_cast<const float4*>(&bias[tx * 4]);
        if (TN == 128) bv1 = *reinterpret_cast<const float4*>(&bias[64 + tx * 4]);
    }
#pragma unroll
    for (int r = 0; r < 8; r++) {
        int m = m0 + ty * 8 + r;
        if (m >= M) continue;
        float rs = (epi == 3) ? g_dinv[m] : 1.0f;
        float f0, f1, f2, f3;
        asm("mov.b64 {%0, %1}, %2;" : "=f"(f0), "=f"(f1) : "l"(acc[r][0]));
        asm("mov.b64 {%0, %1}, %2;" : "=f"(f2), "=f"(f3) : "l"(acc[r][1]));
        float4 o;
        o.x = (f0 + bv0.x) * rs;
        o.y = (f1 + bv0.y) * rs;
        o.z = (f2 + bv0.z) * rs;
        o.w = (f3 + bv0.w) * rs;
        if (epi == 1) {
            o.x = fmaxf(o.x, 0.f); o.y = fmaxf(o.y, 0.f);
            o.z = fmaxf(o.z, 0.f); o.w = fmaxf(o.w, 0.f);
        }
        *reinterpret_cast<float4*>(&C[(size_t)m * TN + tx * 4]) = o;
        if (TN == 128) {
            asm("mov.b64 {%0, %1}, %2;" : "=f"(f0), "=f"(f1) : "l"(acc[r][NPAIR - 2]));
            asm("mov.b64 {%0, %1}, %2;" : "=f"(f2), "=f"(f3) : "l"(acc[r][NPAIR - 1]));
            float4 p;
            p.x = (f0 + bv1.x) * rs;
            p.y = (f1 + bv1.y) * rs;
            p.z = (f2 + bv1.z) * rs;
            p.w = (f3 + bv1.w) * rs;
            if (epi == 1) {
                p.x = fmaxf(p.x, 0.f); p.y = fmaxf(p.y, 0.f);
                p.z = fmaxf(p.z, 0.f); p.w = fmaxf(p.w, 0.f);
            }
            *reinterpret_cast<float4*>(&C[(size_t)m * TN + 64 + tx * 4]) = p;
        }
    }
}

// ---------------- launch ----------------
extern "C" void kernel_launch(void* const* d_in, const int* in_sizes, int n_in,
                              void* d_out, int out_size) {
    const float* x      = (const float*)d_in[0];
    const float* pseudo = (const float*)d_in[1];
    const float* w1     = (const float*)d_in[2];   // [3][64][128] == W1cat [192][128]
    const float* w2     = (const float*)d_in[3];   // [3][128][64] == W2cat [384][64]
    const float* mu_w   = (const float*)d_in[4];
    const float* lv_w   = (const float*)d_in[5];
    const float* d1_w   = (const float*)d_in[6];   // [64][128]
    const float* d1_b   = (const float*)d_in[7];
    const float* d2_w   = (const float*)d_in[8];   // [128][64]
    const float* d2_b   = (const float*)d_in[9];
    const float* eps    = (const float*)d_in[10];
    const void*  ei     = d_in[11];
    float*       out    = (float*)d_out;

    float *py, *ph1, *ph2, *pw3T;
    cudaGetSymbolAddress((void**)&py,   g_y);
    cudaGetSymbolAddress((void**)&ph1,  g_h1);
    cudaGetSymbolAddress((void**)&ph2,  g_h2);
    cudaGetSymbolAddress((void**)&pw3T, g_w3T);

    const int GB = (NN + 127) / 128;

    // --- edge preprocessing: degrees -> CSR offsets -> placement ---
    k_prep<<<SCAN_B, 256>>>((const int*)ei, mu_w, lv_w);
    k_deg<<<(NE + 255) / 256, 256>>>(ei);
    k_scan1<<<SCAN_B, 256>>>();
    k_scan2<<<1, 512>>>();
    k_scan3<<<SCAN_B, 256>>>();
    k_place<<<(NE + 255) / 256, 256>>>(ei, pseudo);

    // --- layer 1: t1 = agg(x); h1 = (t1 @ w1) * dinv ---
    k_agg64<<<(NN * 32 + 255) / 256, 256>>>(x, py);
    k_gemm2<128><<<GB, 256>>>(py, w1, nullptr, ph1, NN, 192, 3, nullptr, nullptr, nullptr);

    // --- layer 2: t2 = agg(h1); h2 = (t2 @ w2) * dinv ---
    k_agg128<<<(NN * 32 + 255) / 256, 256>>>(ph1, py);
    k_gemm2<64><<<GB, 256>>>(py, w2, nullptr, ph2, NN, 384, 3, nullptr, nullptr, nullptr);

    // --- layer 3+4: t3 = agg(h2); fused epilogue: mu/logvar -> out, z -> g_h2 ---
    k_agg64<<<(NN * 32 + 255) / 256, 256>>>(ph2, py);
    k_gemm2<128><<<GB, 256>>>(py, pw3T, nullptr, nullptr, NN, 192, 4, eps, out, ph2);

    // --- decoder: rec = relu(z @ d1_w + d1_b) @ d2_w + d2_b ---
    k_gemm2<128><<<GB, 256>>>(ph2, d1_w, d1_b, py, NN, 64, 1, nullptr, nullptr, nullptr);
    k_gemm2<64><<<GB, 256>>>(py, d2_w, d2_b, out, NN, 128, 2, nullptr, nullptr, nullptr);
}

// round 16
// speedup vs baseline: 1.0215x; 1.0215x over previous
#include <cuda_runtime.h>
#include <cstdint>
#include <cstddef>

#define NN 100000
#define NE 1600000
#define SCAN_B ((NN + 255) / 256)   // 391

typedef unsigned long long ull;

// ---------------- scratch (device globals; zero-initialized at load) ----------------
static __device__ float  g_y[(size_t)NN * 384];     // t buffers [N,K*in] / decoder hidden
static __device__ float  g_h1[(size_t)NN * 128];    // h1
static __device__ float  g_h2[(size_t)NN * 64];     // h2; later z
static __device__ float4 g_ecsr[NE];                // CSR-ordered {c0,c1,c2, src-as-bits}
static __device__ int    g_off[NN + 1];
static __device__ int    g_cur[NN];
static __device__ int    g_deg[NN];
static __device__ float  g_dinv[NN];
static __device__ float  g_w3T[192 * 128];          // [k*64+i][mu 0..63 | logvar 64..127]
static __device__ int    g_bsum[512];
static __device__ int    g_boff[512];
static __device__ int    g_is64;

// ---------------- fused prep: dtype detect + w3 interleave + zero degrees ----------------
__global__ void k_prep(const int* __restrict__ ei32, const float* __restrict__ mw,
                       const float* __restrict__ lw) {
    int idx = blockIdx.x * 256 + threadIdx.x;
    if (blockIdx.x == 0) {
        int nz = (ei32[2 * threadIdx.x + 1] != 0) ? 1 : 0;
        int any = __syncthreads_or(nz);
        if (threadIdx.x == 0) g_is64 = any ? 0 : 1;
    }
    if (idx < 3 * 64 * 64) {
        int o = idx & 63;
        int r = idx >> 6;
        g_w3T[r * 128 + o]      = mw[idx];
        g_w3T[r * 128 + 64 + o] = lw[idx];
    }
    if (idx < NN) g_deg[idx] = 0;
}

// ---------------- degree count: 2 edges per thread, vector loads ----------------
__global__ void k_deg(const void* __restrict__ eiv) {
    int e = (blockIdx.x * blockDim.x + threadIdx.x) * 2;
    if (e >= NE) return;
    int d0, d1;
    if (g_is64) {
        longlong2 dd = *reinterpret_cast<const longlong2*>((const long long*)eiv + NE + e);
        d0 = (int)dd.x; d1 = (int)dd.y;
    } else {
        int2 dd = *reinterpret_cast<const int2*>((const int*)eiv + NE + e);
        d0 = dd.x; d1 = dd.y;
    }
    d0 = min(max(d0, 0), NN - 1);
    d1 = min(max(d1, 0), NN - 1);
    atomicAdd(&g_deg[d0], 1);
    atomicAdd(&g_deg[d1], 1);
}

// ---------------- two-level scan ----------------
__global__ void k_scan1() {
    __shared__ int ws[8];
    int i = blockIdx.x * 256 + threadIdx.x;
    int lane = threadIdx.x & 31, wid = threadIdx.x >> 5;
    int v = (i < NN) ? g_deg[i] : 0;
    int s = v;
#pragma unroll
    for (int o = 1; o < 32; o <<= 1) {
        int t = __shfl_up_sync(0xFFFFFFFFu, s, o);
        if (lane >= o) s += t;
    }
    if (lane == 31) ws[wid] = s;
    __syncthreads();
    if (threadIdx.x == 0) {
        int tot = 0;
#pragma unroll
        for (int w = 0; w < 8; w++) tot += ws[w];
        g_bsum[blockIdx.x] = tot;
    }
}

__global__ void k_scan2() {
    __shared__ int ws[16];
    int tid = threadIdx.x, lane = tid & 31, wid = tid >> 5;
    int v = (tid < SCAN_B) ? g_bsum[tid] : 0;
    int s = v;
#pragma unroll
    for (int o = 1; o < 32; o <<= 1) {
        int t = __shfl_up_sync(0xFFFFFFFFu, s, o);
        if (lane >= o) s += t;
    }
    if (lane == 31) ws[wid] = s;
    __syncthreads();
    if (wid == 0 && lane < 16) {
        int a = ws[lane];
        int si = a;
#pragma unroll
        for (int o = 1; o < 16; o <<= 1) {
            int t = __shfl_up_sync(0xFFFFu, si, o);
            if (lane >= o) si += t;
        }
        ws[lane] = si - a;
    }
    __syncthreads();
    int incl = ws[wid] + s;
    if (tid < SCAN_B) g_boff[tid] = incl - v;
    if (tid == SCAN_B - 1) g_off[NN] = incl;
}

__global__ void k_scan3() {
    __shared__ int ws[8];
    int i = blockIdx.x * 256 + threadIdx.x;
    int lane = threadIdx.x & 31, wid = threadIdx.x >> 5;
    int v = (i < NN) ? g_deg[i] : 0;
    int s = v;
#pragma unroll
    for (int o = 1; o < 32; o <<= 1) {
        int t = __shfl_up_sync(0xFFFFFFFFu, s, o);
        if (lane >= o) s += t;
    }
    if (lane == 31) ws[wid] = s;
    __syncthreads();
    if (wid == 0 && lane < 8) {
        int a = ws[lane];
        int si = a;
#pragma unroll
        for (int o = 1; o < 8; o <<= 1) {
            int t = __shfl_up_sync(0xFFu, si, o);
            if (lane >= o) si += t;
        }
        ws[lane] = si - a;
    }
    __syncthreads();
    if (i < NN) {
        int excl = g_boff[blockIdx.x] + ws[wid] + s - v;
        g_off[i] = excl;
        g_cur[i] = excl;
        g_dinv[i] = 1.0f / fmaxf((float)v, 1.0f);
    }
}

// ---------------- basis + CSR placement: 2 edges per thread, vector loads ----------------
__device__ __forceinline__ float4 edge_meta(float p, int s) {
    float v  = p * 3.0f;
    float fl = floorf(v);
    float f  = v - fl;
    int bot  = ((int)fl) % 3;
    float b0 = 0.5f * f * f - f + 0.5f;
    float b1 = -f * f + f + 0.5f;
    float b2 = 0.5f * f * f;
    float c0, c1, c2;
    if (bot == 0)      { c0 = b0; c1 = b1; c2 = b2; }
    else if (bot == 1) { c0 = b2; c1 = b0; c2 = b1; }
    else               { c0 = b1; c1 = b2; c2 = b0; }
    return make_float4(c0, c1, c2, __int_as_float(s));
}

__global__ void k_place(const void* __restrict__ eiv, const float* __restrict__ pseudo) {
    int e = (blockIdx.x * blockDim.x + threadIdx.x) * 2;
    if (e >= NE) return;
    int s0, s1, d0, d1;
    if (g_is64) {
        longlong2 ss = *reinterpret_cast<const longlong2*>((const long long*)eiv + e);
        longlong2 dd = *reinterpret_cast<const longlong2*>((const long long*)eiv + NE + e);
        s0 = (int)ss.x; s1 = (int)ss.y; d0 = (int)dd.x; d1 = (int)dd.y;
    } else {
        int2 ss = *reinterpret_cast<const int2*>((const int*)eiv + e);
        int2 dd = *reinterpret_cast<const int2*>((const int*)eiv + NE + e);
        s0 = ss.x; s1 = ss.y; d0 = dd.x; d1 = dd.y;
    }
    s0 = min(max(s0, 0), NN - 1); s1 = min(max(s1, 0), NN - 1);
    d0 = min(max(d0, 0), NN - 1); d1 = min(max(d1, 0), NN - 1);
    float2 pp = *reinterpret_cast<const float2*>(pseudo + e);
    int p0 = atomicAdd(&g_cur[d0], 1);
    g_ecsr[p0] = edge_meta(pp.x, s0);
    int p1 = atomicAdd(&g_cur[d1], 1);
    g_ecsr[p1] = edge_meta(pp.y, s1);
}

// ---------------- CSR in-domain aggregation (fp32), unroll x4 (R8-proven) ----------------
#define AGG_FMA(a0, a1, a2, m, v)                                            \
    a0.x += m.x * v.x; a0.y += m.x * v.y; a0.z += m.x * v.z; a0.w += m.x * v.w; \
    a1.x += m.y * v.x; a1.y += m.y * v.y; a1.z += m.y * v.z; a1.w += m.y * v.w; \
    a2.x += m.z * v.x; a2.y += m.z * v.y; a2.z += m.z * v.z; a2.w += m.z * v.w;

__global__ void k_agg64(const float* __restrict__ h, float* __restrict__ t) {
    int lane = threadIdx.x & 15;
    int dst  = (blockIdx.x * blockDim.x + threadIdx.x) >> 4;
    if (dst >= NN) return;
    int p = g_off[dst], end = g_off[dst + 1];
    float4 a0 = make_float4(0.f, 0.f, 0.f, 0.f), a1 = a0, a2 = a0;
    for (; p + 3 < end; p += 4) {
        float4 m0 = g_ecsr[p], m1 = g_ecsr[p + 1], m2 = g_ecsr[p + 2], m3 = g_ecsr[p + 3];
        float4 v0 = *reinterpret_cast<const float4*>(h + ((size_t)__float_as_int(m0.w)) * 64 + lane * 4);
        float4 v1 = *reinterpret_cast<const float4*>(h + ((size_t)__float_as_int(m1.w)) * 64 + lane * 4);
        float4 v2 = *reinterpret_cast<const float4*>(h + ((size_t)__float_as_int(m2.w)) * 64 + lane * 4);
        float4 v3 = *reinterpret_cast<const float4*>(h + ((size_t)__float_as_int(m3.w)) * 64 + lane * 4);
        AGG_FMA(a0, a1, a2, m0, v0)
        AGG_FMA(a0, a1, a2, m1, v1)
        AGG_FMA(a0, a1, a2, m2, v2)
        AGG_FMA(a0, a1, a2, m3, v3)
    }
    for (; p < end; p++) {
        float4 m = g_ecsr[p];
        float4 v = *reinterpret_cast<const float4*>(h + ((size_t)__float_as_int(m.w)) * 64 + lane * 4);
        AGG_FMA(a0, a1, a2, m, v)
    }
    float4* tr = reinterpret_cast<float4*>(t + (size_t)dst * 192);
    tr[lane] = a0; tr[16 + lane] = a1; tr[32 + lane] = a2;
}

__global__ void k_agg128(const float* __restrict__ h, float* __restrict__ t) {
    int lane = threadIdx.x & 31;
    int dst  = (blockIdx.x * blockDim.x + threadIdx.x) >> 5;
    if (dst >= NN) return;
    int p = g_off[dst], end = g_off[dst + 1];
    float4 a0 = make_float4(0.f, 0.f, 0.f, 0.f), a1 = a0, a2 = a0;
    for (; p + 3 < end; p += 4) {
        float4 m0 = g_ecsr[p], m1 = g_ecsr[p + 1], m2 = g_ecsr[p + 2], m3 = g_ecsr[p + 3];
        float4 v0 = *reinterpret_cast<const float4*>(h + ((size_t)__float_as_int(m0.w)) * 128 + lane * 4);
        float4 v1 = *reinterpret_cast<const float4*>(h + ((size_t)__float_as_int(m1.w)) * 128 + lane * 4);
        float4 v2 = *reinterpret_cast<const float4*>(h + ((size_t)__float_as_int(m2.w)) * 128 + lane * 4);
        float4 v3 = *reinterpret_cast<const float4*>(h + ((size_t)__float_as_int(m3.w)) * 128 + lane * 4);
        AGG_FMA(a0, a1, a2, m0, v0)
        AGG_FMA(a0, a1, a2, m1, v1)
        AGG_FMA(a0, a1, a2, m2, v2)
        AGG_FMA(a0, a1, a2, m3, v3)
    }
    for (; p < end; p++) {
        float4 m = g_ecsr[p];
        float4 v = *reinterpret_cast<const float4*>(h + ((size_t)__float_as_int(m.w)) * 128 + lane * 4);
        AGG_FMA(a0, a1, a2, m, v)
    }
    float4* tr = reinterpret_cast<float4*>(t + (size_t)dst * 384);
    tr[lane] = a0; tr[32 + lane] = a1; tr[64 + lane] = a2;
}

// ---------------- GEMM: packed f32x2 math + register double-buffering (750.3µs-proven) ----------------
// C[M,TN] = A[M,K] @ B[K,TN], TM=128, TK=32, 256 threads, 8 rows x TN/16 cols/thread.
// epi: 0 none, 1 bias+relu, 2 bias, 3 row-scale dinv, 4 fused mu/logvar/z (TN=128 only)
template <int TN>
__global__ __launch_bounds__(256, 2) void k_gemm2(
    const float* __restrict__ A, const float* __restrict__ B,
    const float* __restrict__ bias, float* __restrict__ C, int M, int K, int epi,
    const float* __restrict__ eps, float* __restrict__ outmlv, float* __restrict__ zout) {
    constexpr int TK = 32;
    constexpr int NPAIR = TN / 32;
    constexpr int NB = TN / 32;
    __shared__ float As[TK * 132];
    __shared__ float Bs[TK * TN];

    int tid = threadIdx.x;
    int tx  = tid & 15;
    int ty  = tid >> 4;
    int m0  = blockIdx.x * 128;

    float  ar[16];
    float4 br[NB];

#pragma unroll
    for (int i = 0; i < 16; i++) {
        int idx = tid + i * 256;
        int gm = m0 + (idx >> 5);
        ar[i] = (gm < M) ? A[(size_t)gm * K + (idx & 31)] : 0.0f;
    }
#pragma unroll
    for (int i = 0; i < NB; i++) {
        int idx = tid + i * 256;
        br[i] = *reinterpret_cast<const float4*>(&B[(size_t)(idx / (TN / 4)) * TN + (idx % (TN / 4)) * 4]);
    }

    ull acc[8][NPAIR];
#pragma unroll
    for (int r = 0; r < 8; r++)
#pragma unroll
        for (int c = 0; c < NPAIR; c++) acc[r][c] = 0ull;

    for (int kc = 0; kc < K; kc += TK) {
#pragma unroll
        for (int i = 0; i < 16; i++) {
            int idx = tid + i * 256;
            As[(idx & 31) * 132 + (idx >> 5)] = ar[i];
        }
#pragma unroll
        for (int i = 0; i < NB; i++) {
            int idx = tid + i * 256;
            *reinterpret_cast<float4*>(&Bs[(idx / (TN / 4)) * TN + (idx % (TN / 4)) * 4]) = br[i];
        }
        __syncthreads();
        if (kc + TK < K) {
            int kn = kc + TK;
#pragma unroll
            for (int i = 0; i < 16; i++) {
                int idx = tid + i * 256;
                int gm = m0 + (idx >> 5);
                ar[i] = (gm < M) ? A[(size_t)gm * K + kn + (idx & 31)] : 0.0f;
            }
#pragma unroll
            for (int i = 0; i < NB; i++) {
                int idx = tid + i * 256;
                br[i] = *reinterpret_cast<const float4*>(&B[(size_t)(kn + idx / (TN / 4)) * TN + (idx % (TN / 4)) * 4]);
            }
        }
#pragma unroll 8
        for (int k = 0; k < TK; k++) {
            float4 a0 = *reinterpret_cast<const float4*>(&As[k * 132 + ty * 8]);
            float4 a1 = *reinterpret_cast<const float4*>(&As[k * 132 + ty * 8 + 4]);
            float am[8] = {a0.x, a0.y, a0.z, a0.w, a1.x, a1.y, a1.z, a1.w};
            ull ap[8];
#pragma unroll
            for (int r = 0; r < 8; r++)
                asm("mov.b64 %0, {%1, %1};" : "=l"(ap[r]) : "f"(am[r]));
            ulonglong2 b0 = *reinterpret_cast<const ulonglong2*>(&Bs[k * TN + tx * 4]);
#pragma unroll
            for (int r = 0; r < 8; r++) {
                asm("fma.rn.f32x2 %0, %1, %2, %0;" : "+l"(acc[r][0]) : "l"(ap[r]), "l"(b0.x));
                asm("fma.rn.f32x2 %0, %1, %2, %0;" : "+l"(acc[r][1]) : "l"(ap[r]), "l"(b0.y));
            }
            if (TN == 128) {
                ulonglong2 b1 = *reinterpret_cast<const ulonglong2*>(&Bs[k * TN + 64 + tx * 4]);
#pragma unroll
                for (int r = 0; r < 8; r++) {
                    asm("fma.rn.f32x2 %0, %1, %2, %0;" : "+l"(acc[r][NPAIR - 2]) : "l"(ap[r]), "l"(b1.x));
                    asm("fma.rn.f32x2 %0, %1, %2, %0;" : "+l"(acc[r][NPAIR - 1]) : "l"(ap[r]), "l"(b1.y));
                }
            }
        }
        __syncthreads();
    }

    // ---------------- epilogue ----------------
    if (epi == 4) {  // fused: mu | logvar -> outmlv, z -> zout  (TN==128)
        const size_t n64 = (size_t)NN * 64;
#pragma unroll
        for (int r = 0; r < 8; r++) {
            int m = m0 + ty * 8 + r;
            if (m >= M) continue;
            float rs = g_dinv[m];
            float mu0, mu1, mu2, mu3, lv0, lv1, lv2, lv3;
            asm("mov.b64 {%0, %1}, %2;" : "=f"(mu0), "=f"(mu1) : "l"(acc[r][0]));
            asm("mov.b64 {%0, %1}, %2;" : "=f"(mu2), "=f"(mu3) : "l"(acc[r][1]));
            asm("mov.b64 {%0, %1}, %2;" : "=f"(lv0), "=f"(lv1) : "l"(acc[r][NPAIR - 2]));
            asm("mov.b64 {%0, %1}, %2;" : "=f"(lv2), "=f"(lv3) : "l"(acc[r][NPAIR - 1]));
            mu0 *= rs; mu1 *= rs; mu2 *= rs; mu3 *= rs;
            lv0 *= rs; lv1 *= rs; lv2 *= rs; lv3 *= rs;
            size_t base = (size_t)m * 64 + tx * 4;
            float4 ev = *reinterpret_cast<const float4*>(&eps[base]);
            float4 zv;
            zv.x = mu0 + ev.x * expf(0.5f * lv0);
            zv.y = mu1 + ev.y * expf(0.5f * lv1);
            zv.z = mu2 + ev.z * expf(0.5f * lv2);
            zv.w = mu3 + ev.w * expf(0.5f * lv3);
            *reinterpret_cast<float4*>(&outmlv[n64 + base])     = make_float4(mu0, mu1, mu2, mu3);
            *reinterpret_cast<float4*>(&outmlv[2 * n64 + base]) = make_float4(lv0, lv1, lv2, lv3);
            *reinterpret_cast<float4*>(&zout[base]) = zv;
        }
        return;
    }

    float4 bv0 = make_float4(0.f, 0.f, 0.f, 0.f), bv1 = bv0;
    if (epi == 1 || epi == 2) {
        bv0 = *reinterpret_cast<const float4*>(&bias[tx * 4]);
        if (TN == 128) bv1 = *reinterpret_cast<const float4*>(&bias[64 + tx * 4]);
    }
#pragma unroll
    for (int r = 0; r < 8; r++) {
        int m = m0 + ty * 8 + r;
        if (m >= M) continue;
        float rs = (epi == 3) ? g_dinv[m] : 1.0f;
        float f0, f1, f2, f3;
        asm("mov.b64 {%0, %1}, %2;" : "=f"(f0), "=f"(f1) : "l"(acc[r][0]));
        asm("mov.b64 {%0, %1}, %2;" : "=f"(f2), "=f"(f3) : "l"(acc[r][1]));
        float4 o;
        o.x = (f0 + bv0.x) * rs;
        o.y = (f1 + bv0.y) * rs;
        o.z = (f2 + bv0.z) * rs;
        o.w = (f3 + bv0.w) * rs;
        if (epi == 1) {
            o.x = fmaxf(o.x, 0.f); o.y = fmaxf(o.y, 0.f);
            o.z = fmaxf(o.z, 0.f); o.w = fmaxf(o.w, 0.f);
        }
        *reinterpret_cast<float4*>(&C[(size_t)m * TN + tx * 4]) = o;
        if (TN == 128) {
            asm("mov.b64 {%0, %1}, %2;" : "=f"(f0), "=f"(f1) : "l"(acc[r][NPAIR - 2]));
            asm("mov.b64 {%0, %1}, %2;" : "=f"(f2), "=f"(f3) : "l"(acc[r][NPAIR - 1]));
            float4 p;
            p.x = (f0 + bv1.x) * rs;
            p.y = (f1 + bv1.y) * rs;
            p.z = (f2 + bv1.z) * rs;
            p.w = (f3 + bv1.w) * rs;
            if (epi == 1) {
                p.x = fmaxf(p.x, 0.f); p.y = fmaxf(p.y, 0.f);
                p.z = fmaxf(p.z, 0.f); p.w = fmaxf(p.w, 0.f);
            }
            *reinterpret_cast<float4*>(&C[(size_t)m * TN + 64 + tx * 4]) = p;
        }
    }
}

// ---------------- launch ----------------
extern "C" void kernel_launch(void* const* d_in, const int* in_sizes, int n_in,
                              void* d_out, int out_size) {
    const float* x      = (const float*)d_in[0];
    const float* pseudo = (const float*)d_in[1];
    const float* w1     = (const float*)d_in[2];   // [3][64][128] == W1cat [192][128]
    const float* w2     = (const float*)d_in[3];   // [3][128][64] == W2cat [384][64]
    const float* mu_w   = (const float*)d_in[4];
    const float* lv_w   = (const float*)d_in[5];
    const float* d1_w   = (const float*)d_in[6];   // [64][128]
    const float* d1_b   = (const float*)d_in[7];
    const float* d2_w   = (const float*)d_in[8];   // [128][64]
    const float* d2_b   = (const float*)d_in[9];
    const float* eps    = (const float*)d_in[10];
    const void*  ei     = d_in[11];
    float*       out    = (float*)d_out;

    float *py, *ph1, *ph2, *pw3T;
    cudaGetSymbolAddress((void**)&py,   g_y);
    cudaGetSymbolAddress((void**)&ph1,  g_h1);
    cudaGetSymbolAddress((void**)&ph2,  g_h2);
    cudaGetSymbolAddress((void**)&pw3T, g_w3T);

    const int GB = (NN + 127) / 128;

    // --- edge preprocessing: degrees -> CSR offsets -> placement ---
    k_prep<<<SCAN_B, 256>>>((const int*)ei, mu_w, lv_w);
    k_deg<<<(NE / 2 + 255) / 256, 256>>>(ei);
    k_scan1<<<SCAN_B, 256>>>();
    k_scan2<<<1, 512>>>();
    k_scan3<<<SCAN_B, 256>>>();
    k_place<<<(NE / 2 + 255) / 256, 256>>>(ei, pseudo);

    // --- layer 1: t1 = agg(x); h1 = (t1 @ w1) * dinv ---
    k_agg64<<<(NN * 16 + 255) / 256, 256>>>(x, py);
    k_gemm2<128><<<GB, 256>>>(py, w1, nullptr, ph1, NN, 192, 3, nullptr, nullptr, nullptr);

    // --- layer 2: t2 = agg(h1); h2 = (t2 @ w2) * dinv ---
    k_agg128<<<(NN * 32 + 255) / 256, 256>>>(ph1, py);
    k_gemm2<64><<<GB, 256>>>(py, w2, nullptr, ph2, NN, 384, 3, nullptr, nullptr, nullptr);

    // --- layer 3+4: t3 = agg(h2); fused epilogue: mu/logvar -> out, z -> g_h2 ---
    k_agg64<<<(NN * 16 + 255) / 256, 256>>>(ph2, py);
    k_gemm2<128><<<GB, 256>>>(py, pw3T, nullptr, nullptr, NN, 192, 4, eps, out, ph2);

    // --- decoder: rec = relu(z @ d1_w + d1_b) @ d2_w + d2_b ---
    k_gemm2<128><<<GB, 256>>>(ph2, d1_w, d1_b, py, NN, 64, 1, nullptr, nullptr, nullptr);
    k_gemm2<64><<<GB, 256>>>(py, d2_w, d2_b, out, NN, 128, 2, nullptr, nullptr, nullptr);
}